// round 6
// baseline (speedup 1.0000x reference)
#include <cuda_runtime.h>

#define NMAX   160000
#define KCOUT  32
#define KCIN   32
#define KTAPS  27
#define WELEMS (KTAPS * KCIN * KCOUT)   // 27648
#define BLOCKS1 1480                    // conv grid: 8 warps/block

// ---- device scratch (no allocations allowed) ----
__device__ float g_conv[(size_t)NMAX * KCOUT];   // pre-BN conv output (20.5 MB)
__device__ float g_wt[WELEMS];                   // transposed weights [k][c/4][d][c%4]
__device__ float g_psum[BLOCKS1 * KCOUT];        // per-block channel sums
__device__ float g_psq [BLOCKS1 * KCOUT];        // per-block channel sum-of-squares
__device__ float g_scale[KCOUT];                 // rstd * gamma
__device__ float g_shift[KCOUT];                 // beta - mean * scale

// ---------------------------------------------------------------------------
// K0: transpose weight [k][c][d] -> [k][c>>2][d][c&3] so that lane d can load
//     a float4 covering 4 consecutive c for its output channel (coalesced).
// ---------------------------------------------------------------------------
__global__ void transpose_w_kernel(const float* __restrict__ w) {
    int i = blockIdx.x * blockDim.x + threadIdx.x;
    if (i < WELEMS) {
        int d = i & 31;
        int c = (i >> 5) & 31;
        int k = i >> 10;
        g_wt[k * 1024 + (c >> 2) * 128 + d * 4 + (c & 3)] = w[i];
    }
}

// ---------------------------------------------------------------------------
// K1: warp-per-row sparse conv + bias; accumulates per-block BN partials.
// ---------------------------------------------------------------------------
__global__ __launch_bounds__(256) void conv_kernel(
    const float* __restrict__ feat,   // [N,32]
    const int*   __restrict__ nbr,    // [N,27]
    const float* __restrict__ bias,   // [32]
    int n)
{
    const int lane  = threadIdx.x & 31;
    const int wloc  = threadIdx.x >> 5;                 // warp in block (0..7)
    const int warp  = blockIdx.x * 8 + wloc;
    const int nwarp = gridDim.x * 8;

    const float bv = __ldg(bias + lane);
    float bsum = 0.f, bsq = 0.f;

    for (int row = warp; row < n; row += nwarp) {
        int idx = -1;
        if (lane < KTAPS) idx = __ldg(nbr + (long)row * KTAPS + lane);
        unsigned m = __ballot_sync(0xffffffffu, idx >= 0);

        float acc = 0.f;
        while (m) {
            int k = __ffs(m) - 1;
            m &= (m - 1);
            int j = __shfl_sync(0xffffffffu, idx, k);

            const float4* fp = (const float4*)(feat + (long)j * 32);  // broadcast
            const float4* wp = (const float4*)(g_wt + k * 1024) + lane; // coalesced

            float4 f[8];
            #pragma unroll
            for (int t = 0; t < 8; ++t) f[t] = __ldg(fp + t);

            #pragma unroll
            for (int c4 = 0; c4 < 8; ++c4) {
                float4 w = __ldg(wp + c4 * 32);   // W[k][4*c4..4*c4+3][lane]
                acc += f[c4].x * w.x + f[c4].y * w.y
                     + f[c4].z * w.z + f[c4].w * w.w;
            }
        }

        float v = acc + bv;
        g_conv[(long)row * KCOUT + lane] = v;
        bsum += v;
        bsq  += v * v;
    }

    // block-level deterministic reduction of BN partials
    __shared__ float s_sum[8][32];
    __shared__ float s_sq [8][32];
    s_sum[wloc][lane] = bsum;
    s_sq [wloc][lane] = bsq;
    __syncthreads();
    if (threadIdx.x < 32) {
        float s = 0.f, q = 0.f;
        #pragma unroll
        for (int i = 0; i < 8; ++i) { s += s_sum[i][threadIdx.x]; q += s_sq[i][threadIdx.x]; }
        g_psum[blockIdx.x * 32 + threadIdx.x] = s;
        g_psq [blockIdx.x * 32 + threadIdx.x] = q;
    }
}

// ---------------------------------------------------------------------------
// K2: reduce block partials -> mean/var -> fused scale/shift. Single block.
// ---------------------------------------------------------------------------
__global__ void stats_kernel(const float* __restrict__ gamma,
                             const float* __restrict__ beta,
                             int n)
{
    __shared__ float ss[16][32];
    __shared__ float sq[16][32];
    const int ch = threadIdx.x & 31;
    const int sl = threadIdx.x >> 5;   // 512 threads -> 16 slices

    float s = 0.f, q = 0.f;
    for (int i = sl; i < BLOCKS1; i += 16) {
        s += g_psum[i * 32 + ch];
        q += g_psq [i * 32 + ch];
    }
    ss[sl][ch] = s;
    sq[sl][ch] = q;
    __syncthreads();

    if (threadIdx.x < 32) {
        float S = 0.f, Q = 0.f;
        #pragma unroll
        for (int i = 0; i < 16; ++i) { S += ss[i][threadIdx.x]; Q += sq[i][threadIdx.x]; }
        float inv_n = 1.f / (float)n;
        float mean  = S * inv_n;
        float var   = Q * inv_n - mean * mean;
        float rstd  = rsqrtf(var + 1e-5f);
        float sc    = rstd * __ldg(gamma + threadIdx.x);
        g_scale[threadIdx.x] = sc;
        g_shift[threadIdx.x] = __ldg(beta + threadIdx.x) - mean * sc;
    }
}

// ---------------------------------------------------------------------------
// K3: elementwise BN-apply + LeakyReLU, float4 vectorized (32 | 4).
// ---------------------------------------------------------------------------
__global__ __launch_bounds__(256) void finalize_kernel(float* __restrict__ out, int n4) {
    int i = blockIdx.x * blockDim.x + threadIdx.x;
    if (i >= n4) return;
    float4 v = ((const float4*)g_conv)[i];
    int cb = (i & 7) * 4;                       // channel base within row
    float4 sc = *(const float4*)(g_scale + cb);
    float4 sh = *(const float4*)(g_shift + cb);
    float4 o;
    o.x = v.x * sc.x + sh.x;
    o.y = v.y * sc.y + sh.y;
    o.z = v.z * sc.z + sh.z;
    o.w = v.w * sc.w + sh.w;
    o.x = (o.x >= 0.f) ? o.x : 0.01f * o.x;
    o.y = (o.y >= 0.f) ? o.y : 0.01f * o.y;
    o.z = (o.z >= 0.f) ? o.z : 0.01f * o.z;
    o.w = (o.w >= 0.f) ? o.w : 0.01f * o.w;
    ((float4*)out)[i] = o;
}

// ---------------------------------------------------------------------------
// kernel_launch — inputs per metadata order:
//   0: features [N,32] f32   1: neighbor_idx [N,27] i32   2: weight [27,32,32] f32
//   3: bias [32] f32         4: gamma [32] f32            5: beta [32] f32
// output: [N,32] f32
// ---------------------------------------------------------------------------
extern "C" void kernel_launch(void* const* d_in, const int* in_sizes, int n_in,
                              void* d_out, int out_size)
{
    const float* feat  = (const float*)d_in[0];
    const int*   nbr   = (const int*)  d_in[1];
    const float* w     = (const float*)d_in[2];
    const float* bias  = (const float*)d_in[3];
    const float* gamma = (const float*)d_in[4];
    const float* beta  = (const float*)d_in[5];
    float* out = (float*)d_out;

    int n = in_sizes[0] / KCIN;     // number of active voxels
    if (n > NMAX) n = NMAX;

    transpose_w_kernel<<<(WELEMS + 255) / 256, 256>>>(w);
    conv_kernel<<<BLOCKS1, 256>>>(feat, nbr, bias, n);
    stats_kernel<<<1, 512>>>(gamma, beta, n);
    int n4 = n * (KCOUT / 4);
    finalize_kernel<<<(n4 + 255) / 256, 256>>>(out, n4);
}

// round 7
// speedup vs baseline: 1.1007x; 1.1007x over previous
#include <cuda_runtime.h>

#define NMAX    160000
#define KCOUT   32
#define KCIN    32
#define KTAPS   27
#define WELEMS  (KTAPS * KCIN * KCOUT)   // 27648
#define CBLOCKS 2960                     // conv grid: 4 warps/block

// ---- device scratch (no allocations allowed) ----
__device__ float g_conv[(size_t)NMAX * KCOUT];   // pre-BN conv output (20.5 MB)
__device__ float g_wt[WELEMS];                   // transposed weights [k][c/4][d][c%4]
__device__ float g_psum[CBLOCKS * KCOUT];        // per-block channel sums
__device__ float g_psq [CBLOCKS * KCOUT];        // per-block channel sum-of-squares
__device__ float g_scale[KCOUT];                 // rstd * gamma
__device__ float g_shift[KCOUT];                 // beta - mean * scale

// ---------------------------------------------------------------------------
// K0: transpose weight [k][c][d] -> [k][c>>2][d][c&3] so that lane d can load
//     a float4 covering 4 consecutive c for its output channel (coalesced).
// ---------------------------------------------------------------------------
__global__ void transpose_w_kernel(const float* __restrict__ w) {
    int i = blockIdx.x * blockDim.x + threadIdx.x;
    if (i < WELEMS) {
        int d = i & 31;
        int c = (i >> 5) & 31;
        int k = i >> 10;
        g_wt[k * 1024 + (c >> 2) * 128 + d * 4 + (c & 3)] = w[i];
    }
}

// ---------------------------------------------------------------------------
// K1: warp-per-row sparse conv + bias; center-tap weights register-resident,
//     next-row index prefetch; accumulates per-block BN partials.
// ---------------------------------------------------------------------------
__global__ __launch_bounds__(128) void conv_kernel(
    const float* __restrict__ feat,   // [N,32]
    const int*   __restrict__ nbr,    // [N,27]
    const float* __restrict__ bias,   // [32]
    int n)
{
    const int lane  = threadIdx.x & 31;
    const int wloc  = threadIdx.x >> 5;                 // warp in block (0..3)
    const int warp  = blockIdx.x * 4 + wloc;
    const int nwarp = gridDim.x * 4;

    // Center-tap (k=13) weights: lane d holds W[13][c][d] for all c, in regs.
    const float4* wcp = (const float4*)(g_wt + 13 * 1024) + lane;
    float4 wc[8];
    #pragma unroll
    for (int c4 = 0; c4 < 8; ++c4) wc[c4] = __ldg(wcp + c4 * 32);

    const float bv = __ldg(bias + lane);
    float bsum = 0.f, bsq = 0.f;

    int row = warp;
    int idx = -1;
    if (row < n && lane < KTAPS) idx = __ldg(nbr + (long)row * KTAPS + lane);

    while (row < n) {
        // prefetch next row's neighbor indices (hides the ~600cy idx latency)
        const int nrow = row + nwarp;
        int nidx = -1;
        if (nrow < n && lane < KTAPS)
            nidx = __ldg(nbr + (long)nrow * KTAPS + lane);

        unsigned m = __ballot_sync(0xffffffffu, idx >= 0);
        const int jc = __shfl_sync(0xffffffffu, idx, 13);  // center: always valid
        m &= ~(1u << 13);

        // center tap: broadcast feature row, register weights, no L1 W traffic
        const float4* fp = (const float4*)(feat + (long)jc * 32);
        float4 f[8];
        #pragma unroll
        for (int t = 0; t < 8; ++t) f[t] = __ldg(fp + t);
        float acc = 0.f;
        #pragma unroll
        for (int c4 = 0; c4 < 8; ++c4)
            acc += f[c4].x * wc[c4].x + f[c4].y * wc[c4].y
                 + f[c4].z * wc[c4].z + f[c4].w * wc[c4].w;

        // rare extra taps (~0.49/row): loaded weight path
        while (m) {
            int k = __ffs(m) - 1;
            m &= (m - 1);
            int j = __shfl_sync(0xffffffffu, idx, k);

            const float4* fp2 = (const float4*)(feat + (long)j * 32);
            const float4* wp  = (const float4*)(g_wt + k * 1024) + lane;

            float4 f2[8];
            #pragma unroll
            for (int t = 0; t < 8; ++t) f2[t] = __ldg(fp2 + t);

            #pragma unroll
            for (int c4 = 0; c4 < 8; ++c4) {
                float4 w = __ldg(wp + c4 * 32);
                acc += f2[c4].x * w.x + f2[c4].y * w.y
                     + f2[c4].z * w.z + f2[c4].w * w.w;
            }
        }

        float v = acc + bv;
        g_conv[(long)row * KCOUT + lane] = v;
        bsum += v;
        bsq  += v * v;

        row = nrow;
        idx = nidx;
    }

    // block-level deterministic reduction of BN partials
    __shared__ float s_sum[4][32];
    __shared__ float s_sq [4][32];
    s_sum[wloc][lane] = bsum;
    s_sq [wloc][lane] = bsq;
    __syncthreads();
    if (threadIdx.x < 32) {
        float s = 0.f, q = 0.f;
        #pragma unroll
        for (int i = 0; i < 4; ++i) { s += s_sum[i][threadIdx.x]; q += s_sq[i][threadIdx.x]; }
        g_psum[blockIdx.x * 32 + threadIdx.x] = s;
        g_psq [blockIdx.x * 32 + threadIdx.x] = q;
    }
}

// ---------------------------------------------------------------------------
// K2: reduce block partials -> mean/var -> fused scale/shift. Single block.
// ---------------------------------------------------------------------------
__global__ void stats_kernel(const float* __restrict__ gamma,
                             const float* __restrict__ beta,
                             int n)
{
    __shared__ float ss[32][32];
    __shared__ float sq[32][32];
    const int ch = threadIdx.x & 31;
    const int sl = threadIdx.x >> 5;   // 1024 threads -> 32 slices

    float s = 0.f, q = 0.f;
    for (int i = sl; i < CBLOCKS; i += 32) {
        s += g_psum[i * 32 + ch];
        q += g_psq [i * 32 + ch];
    }
    ss[sl][ch] = s;
    sq[sl][ch] = q;
    __syncthreads();

    if (threadIdx.x < 32) {
        float S = 0.f, Q = 0.f;
        #pragma unroll
        for (int i = 0; i < 32; ++i) { S += ss[i][threadIdx.x]; Q += sq[i][threadIdx.x]; }
        float inv_n = 1.f / (float)n;
        float mean  = S * inv_n;
        float var   = Q * inv_n - mean * mean;
        float rstd  = rsqrtf(var + 1e-5f);
        float sc    = rstd * __ldg(gamma + threadIdx.x);
        g_scale[threadIdx.x] = sc;
        g_shift[threadIdx.x] = __ldg(beta + threadIdx.x) - mean * sc;
    }
}

// ---------------------------------------------------------------------------
// K3: elementwise BN-apply + LeakyReLU, float4 vectorized, ILP=4.
// ---------------------------------------------------------------------------
__global__ __launch_bounds__(256) void finalize_kernel(float* __restrict__ out, int n4) {
    const int i0 = blockIdx.x * 1024 + threadIdx.x;

    float4 v[4];
    int    ok[4];
    #pragma unroll
    for (int u = 0; u < 4; ++u) {
        int i = i0 + u * 256;
        ok[u] = (i < n4);
        if (ok[u]) v[u] = ((const float4*)g_conv)[i];
    }

    #pragma unroll
    for (int u = 0; u < 4; ++u) {
        if (!ok[u]) continue;
        int i  = i0 + u * 256;
        int cb = (i & 7) * 4;                     // channel base within row
        float4 sc = *(const float4*)(g_scale + cb);
        float4 sh = *(const float4*)(g_shift + cb);
        float4 o;
        o.x = v[u].x * sc.x + sh.x;
        o.y = v[u].y * sc.y + sh.y;
        o.z = v[u].z * sc.z + sh.z;
        o.w = v[u].w * sc.w + sh.w;
        o.x = (o.x >= 0.f) ? o.x : 0.01f * o.x;
        o.y = (o.y >= 0.f) ? o.y : 0.01f * o.y;
        o.z = (o.z >= 0.f) ? o.z : 0.01f * o.z;
        o.w = (o.w >= 0.f) ? o.w : 0.01f * o.w;
        ((float4*)out)[i] = o;
    }
}

// ---------------------------------------------------------------------------
// kernel_launch — inputs per metadata order:
//   0: features [N,32] f32   1: neighbor_idx [N,27] i32   2: weight [27,32,32] f32
//   3: bias [32] f32         4: gamma [32] f32            5: beta [32] f32
// output: [N,32] f32
// ---------------------------------------------------------------------------
extern "C" void kernel_launch(void* const* d_in, const int* in_sizes, int n_in,
                              void* d_out, int out_size)
{
    const float* feat  = (const float*)d_in[0];
    const int*   nbr   = (const int*)  d_in[1];
    const float* w     = (const float*)d_in[2];
    const float* bias  = (const float*)d_in[3];
    const float* gamma = (const float*)d_in[4];
    const float* beta  = (const float*)d_in[5];
    float* out = (float*)d_out;

    int n = in_sizes[0] / KCIN;     // number of active voxels
    if (n > NMAX) n = NMAX;

    transpose_w_kernel<<<(WELEMS + 255) / 256, 256>>>(w);
    conv_kernel<<<CBLOCKS, 128>>>(feat, nbr, bias, n);
    stats_kernel<<<1, 1024>>>(gamma, beta, n);
    int n4 = n * (KCOUT / 4);
    finalize_kernel<<<(n4 + 1023) / 1024, 256>>>(out, n4);
}

// round 8
// speedup vs baseline: 1.2664x; 1.1506x over previous
#include <cuda_runtime.h>

#define NMAX    160000
#define KCOUT   32
#define KCIN    32
#define KTAPS   27
#define WELEMS  (KTAPS * KCIN * KCOUT)   // 27648
#define CBLOCKS 592                      // conv grid: 4 warps/block -> 2368 warps (1 wave)

// ---- device scratch (no allocations allowed) ----
__device__ float g_conv[(size_t)NMAX * KCOUT];   // pre-BN conv output (20.5 MB)
__device__ float g_wt[WELEMS];                   // transposed weights [k][c/4][d][c%4]
__device__ float g_psum[CBLOCKS * KCOUT];        // per-block channel sums
__device__ float g_psq [CBLOCKS * KCOUT];        // per-block channel sum-of-squares
__device__ float g_scale[KCOUT];                 // rstd * gamma
__device__ float g_shift[KCOUT];                 // beta - mean * scale

// ---------------------------------------------------------------------------
// K0: transpose weight [k][c][d] -> [k][c>>2][d][c&3] so that lane d can load
//     a float4 covering 4 consecutive c for its output channel (coalesced).
// ---------------------------------------------------------------------------
__global__ void transpose_w_kernel(const float* __restrict__ w) {
    int i = blockIdx.x * blockDim.x + threadIdx.x;
    if (i < WELEMS) {
        int d = i & 31;
        int c = (i >> 5) & 31;
        int k = i >> 10;
        g_wt[k * 1024 + (c >> 2) * 128 + d * 4 + (c & 3)] = w[i];
    }
}

// ---------------------------------------------------------------------------
// K1: sparse conv. Center tap (k=13) is ALWAYS the row itself (submanifold),
//     so the dominant path is a dense coalesced stream feat[row]·W13 with
//     register weights — no gather, no shfl, no idx dependency. The idx load
//     only feeds the rare (~0.49/row) extra-tap path and is issued in
//     parallel. One-row software pipeline; contiguous chunk per warp.
//     Bias omitted: training-mode BN cancels any per-channel constant shift.
// ---------------------------------------------------------------------------
__global__ __launch_bounds__(128, 4) void conv_kernel(
    const float* __restrict__ feat,   // [N,32]
    const int*   __restrict__ nbr,    // [N,27]
    int n)
{
    const int lane  = threadIdx.x & 31;
    const int wloc  = threadIdx.x >> 5;                 // warp in block (0..3)
    const int warp  = blockIdx.x * 4 + wloc;
    const int nwarp = CBLOCKS * 4;

    // Center-tap (k=13) weights: lane d holds W[13][c][d] for all c, in regs.
    const float4* wcp = (const float4*)(g_wt + 13 * 1024) + lane;
    float4 wc[8];
    #pragma unroll
    for (int c4 = 0; c4 < 8; ++c4) wc[c4] = __ldg(wcp + c4 * 32);

    const unsigned EXTRA_MASK = ((1u << KTAPS) - 1u) & ~(1u << 13);

    const int per = (n + nwarp - 1) / nwarp;
    const int r0  = warp * per;
    const int r1  = (r0 + per < n) ? (r0 + per) : n;

    float bsum = 0.f, bsq = 0.f;

    if (r0 < r1) {
        // preload first row: features (no index needed!) + neighbor indices
        float4 f[8];
        {
            const float4* fp = (const float4*)(feat + (long)r0 * 32);
            #pragma unroll
            for (int t = 0; t < 8; ++t) f[t] = __ldg(fp + t);
        }
        int idx = (lane < KTAPS) ? __ldg(nbr + (long)r0 * KTAPS + lane) : -1;

        for (int row = r0; row < r1; ++row) {
            // issue next row's loads before any math (pipeline depth 1)
            const int nrow = row + 1;
            float4 fn[8];
            int nidx = -1;
            if (nrow < r1) {
                const float4* fp = (const float4*)(feat + (long)nrow * 32);
                #pragma unroll
                for (int t = 0; t < 8; ++t) fn[t] = __ldg(fp + t);
                nidx = __ldg(nbr + (long)nrow * KTAPS + lane);
                nidx = (lane < KTAPS) ? nidx : -1;
            }

            // center tap: dense, register weights
            float acc = 0.f;
            #pragma unroll
            for (int c4 = 0; c4 < 8; ++c4)
                acc += f[c4].x * wc[c4].x + f[c4].y * wc[c4].y
                     + f[c4].z * wc[c4].z + f[c4].w * wc[c4].w;

            // rare extra taps
            unsigned m = __ballot_sync(0xffffffffu, idx >= 0) & EXTRA_MASK;
            while (m) {
                int k = __ffs(m) - 1;
                m &= (m - 1);
                int j = __shfl_sync(0xffffffffu, idx, k);

                const float4* fp2 = (const float4*)(feat + (long)j * 32);
                const float4* wp  = (const float4*)(g_wt + k * 1024) + lane;

                // two halves of 4 float4s to cap register pressure
                #pragma unroll
                for (int h = 0; h < 2; ++h) {
                    float4 f2[4], w2[4];
                    #pragma unroll
                    for (int t = 0; t < 4; ++t) {
                        f2[t] = __ldg(fp2 + h * 4 + t);
                        w2[t] = __ldg(wp + (h * 4 + t) * 32);
                    }
                    #pragma unroll
                    for (int t = 0; t < 4; ++t)
                        acc += f2[t].x * w2[t].x + f2[t].y * w2[t].y
                             + f2[t].z * w2[t].z + f2[t].w * w2[t].w;
                }
            }

            g_conv[(long)row * KCOUT + lane] = acc;
            bsum += acc;
            bsq  += acc * acc;

            #pragma unroll
            for (int t = 0; t < 8; ++t) f[t] = fn[t];
            idx = nidx;
        }
    }

    // block-level deterministic reduction of BN partials
    __shared__ float s_sum[4][32];
    __shared__ float s_sq [4][32];
    s_sum[wloc][lane] = bsum;
    s_sq [wloc][lane] = bsq;
    __syncthreads();
    if (threadIdx.x < 32) {
        float s = 0.f, q = 0.f;
        #pragma unroll
        for (int i = 0; i < 4; ++i) { s += s_sum[i][threadIdx.x]; q += s_sq[i][threadIdx.x]; }
        g_psum[blockIdx.x * 32 + threadIdx.x] = s;
        g_psq [blockIdx.x * 32 + threadIdx.x] = q;
    }
}

// ---------------------------------------------------------------------------
// K2: reduce block partials -> mean/var -> fused scale/shift. Single block.
// ---------------------------------------------------------------------------
__global__ void stats_kernel(const float* __restrict__ gamma,
                             const float* __restrict__ beta,
                             int n)
{
    __shared__ float ss[32][32];
    __shared__ float sq[32][32];
    const int ch = threadIdx.x & 31;
    const int sl = threadIdx.x >> 5;   // 1024 threads -> 32 slices

    float s = 0.f, q = 0.f;
    for (int i = sl; i < CBLOCKS; i += 32) {
        s += g_psum[i * 32 + ch];
        q += g_psq [i * 32 + ch];
    }
    ss[sl][ch] = s;
    sq[sl][ch] = q;
    __syncthreads();

    if (threadIdx.x < 32) {
        float S = 0.f, Q = 0.f;
        #pragma unroll
        for (int i = 0; i < 32; ++i) { S += ss[i][threadIdx.x]; Q += sq[i][threadIdx.x]; }
        float inv_n = 1.f / (float)n;
        float mean  = S * inv_n;
        float var   = Q * inv_n - mean * mean;
        float rstd  = rsqrtf(var + 1e-5f);
        float sc    = rstd * __ldg(gamma + threadIdx.x);
        g_scale[threadIdx.x] = sc;
        g_shift[threadIdx.x] = __ldg(beta + threadIdx.x) - mean * sc;
    }
}

// ---------------------------------------------------------------------------
// K3: elementwise BN-apply + LeakyReLU, float4 vectorized (simple form —
//     the ILP=4 variant measured slower).
// ---------------------------------------------------------------------------
__global__ __launch_bounds__(256) void finalize_kernel(float* __restrict__ out, int n4) {
    int i = blockIdx.x * blockDim.x + threadIdx.x;
    if (i >= n4) return;
    float4 v = ((const float4*)g_conv)[i];
    int cb = (i & 7) * 4;                       // channel base within row
    float4 sc = *(const float4*)(g_scale + cb);
    float4 sh = *(const float4*)(g_shift + cb);
    float4 o;
    o.x = v.x * sc.x + sh.x;
    o.y = v.y * sc.y + sh.y;
    o.z = v.z * sc.z + sh.z;
    o.w = v.w * sc.w + sh.w;
    o.x = (o.x >= 0.f) ? o.x : 0.01f * o.x;
    o.y = (o.y >= 0.f) ? o.y : 0.01f * o.y;
    o.z = (o.z >= 0.f) ? o.z : 0.01f * o.z;
    o.w = (o.w >= 0.f) ? o.w : 0.01f * o.w;
    ((float4*)out)[i] = o;
}

// ---------------------------------------------------------------------------
// kernel_launch — inputs per metadata order:
//   0: features [N,32] f32   1: neighbor_idx [N,27] i32   2: weight [27,32,32] f32
//   3: bias [32] f32         4: gamma [32] f32            5: beta [32] f32
// output: [N,32] f32     (bias unused: cancelled exactly by training-mode BN)
// ---------------------------------------------------------------------------
extern "C" void kernel_launch(void* const* d_in, const int* in_sizes, int n_in,
                              void* d_out, int out_size)
{
    const float* feat  = (const float*)d_in[0];
    const int*   nbr   = (const int*)  d_in[1];
    const float* w     = (const float*)d_in[2];
    const float* gamma = (const float*)d_in[4];
    const float* beta  = (const float*)d_in[5];
    float* out = (float*)d_out;

    int n = in_sizes[0] / KCIN;     // number of active voxels
    if (n > NMAX) n = NMAX;

    transpose_w_kernel<<<(WELEMS + 255) / 256, 256>>>(w);
    conv_kernel<<<CBLOCKS, 128>>>(feat, nbr, n);
    stats_kernel<<<1, 1024>>>(gamma, beta, n);
    int n4 = n * (KCOUT / 4);
    finalize_kernel<<<(n4 + 255) / 256, 256>>>(out, n4);
}